// round 1
// baseline (speedup 1.0000x reference)
#include <cuda_runtime.h>

// GMMVAE ELBO, fully fused. B=16384, X=784, Z=K=64.
// elbo = (log_px_z - kl_y - kl_z)/B
//
// Algebra used:
//   comp_lp[b,k] = -0.5*(sum_z z^2*s2inv - 2*sum_z z*mu*s2inv) + cc2[k]
//       cc2[k]   = -sum_z ls - 32*LOG2PI - 0.5*sum_z mu^2*s2inv
//   klz[b,k]     =  0.5*(sum_z (qs^2+qmu^2)*s2inv - 2*sum_z qmu*mu*s2inv) + ck2[k]
//                   - sum_z qls[b] - 32
//       ck2[k]   =  sum_z ls + 0.5*sum_z mu^2*s2inv
//   with s2inv = exp(-2*ls).  We store na2 = -2*mu*s2inv so each z-term is 2 FMAs.
//   kl_y[b]      = sum_k probs*(comp_lp - lse)   (since pzy = comp_lp + log pi)

#define B_TOT 16384
#define XD 784
#define ZD 64
#define KK 64
#define ROWS 32
#define THREADS 256
#define NBLK (B_TOT / ROWS)   // 512
#define TILE 112
#define NTILE 7               // 7*112 = 784
#define SP 68                 // padded z-stride (16B aligned, conflict-free LDS.128)
#define LOG2PI 1.8378770664093453

// ---- device scratch (no allocations allowed) ----
__device__ float g_s2inv[KK * ZD];
__device__ float g_na2[KK * ZD];
__device__ float g_cc2[KK];
__device__ float g_ck2[KK];
__device__ float g_part[NBLK];

// smem layout (floats):
//  s2   [64*68]                  4352
//  na2  [64*68]                  4352
//  zbuf [32*64]                  2048
//  qmB  [32*64]                  2048
//  v1B  [32*64]                  2048   (qs^2 + qmu^2)
//  U    max(Wt2[112*68]+bt[112], compS[2048]+klzS[2048]) = 7728
//  red  [16]
#define SMEM_FLOATS (4352 * 2 + 2048 * 3 + 7728 + 16)
#define SMEM_BYTES (SMEM_FLOATS * 4)

__global__ void precomp_kernel(const float* __restrict__ pmu,
                               const float* __restrict__ pls) {
    int k = threadIdx.x;
    if (k >= KK) return;
    float lsum = 0.f, c1 = 0.f;
    for (int z = 0; z < ZD; z++) {
        float ls = pls[k * ZD + z];
        float mu = pmu[k * ZD + z];
        float s2i = expf(-2.f * ls);
        g_s2inv[k * ZD + z] = s2i;
        g_na2[k * ZD + z] = -2.f * mu * s2i;
        lsum += ls;
        c1 = fmaf(mu * mu, s2i, c1);
    }
    g_cc2[k] = (float)(-(double)lsum - 32.0 * LOG2PI - 0.5 * (double)c1);
    g_ck2[k] = lsum + 0.5f * c1;
}

extern __shared__ float smem[];

__global__ __launch_bounds__(THREADS, 2)
void main_kernel(const float* __restrict__ x, const float* __restrict__ pi,
                 const float* __restrict__ qmu, const float* __restrict__ qls,
                 const float* __restrict__ eps, const float* __restrict__ W,
                 const float* __restrict__ bdec) {
    float* s2 = smem;                   // 64*68
    float* na2 = s2 + KK * SP;          // 64*68
    float* zbuf = na2 + KK * SP;        // 32*64
    float* qmB = zbuf + ROWS * ZD;      // 32*64
    float* v1B = qmB + ROWS * ZD;       // 32*64
    float* U = v1B + ROWS * ZD;         // union region
    float* Wt2 = U;                     // [112][68] transposed W tile
    float* bt = U + TILE * SP;          // [112]
    float* compS = U;                   // [32][64]  (after GEMM stage)
    float* klzS = U + ROWS * KK;        // [32][64]
    float* red = U + TILE * SP + TILE;  // [16]

    const int tid = threadIdx.x;
    const int rowbase = blockIdx.x * ROWS;

    // ---- load per-k arrays into padded smem ----
    for (int i = tid; i < KK * ZD; i += THREADS) {
        int k = i >> 6, z = i & 63;
        s2[k * SP + z] = g_s2inv[i];
        na2[k * SP + z] = g_na2[i];
    }
    // ---- load per-row data, build z, qmu, qs^2+qmu^2 ----
    for (int i = tid; i < ROWS * ZD; i += THREADS) {
        int gi = (rowbase + (i >> 6)) * ZD + (i & 63);
        float qm = qmu[gi];
        float ql = qls[gi];
        float qs = expf(ql);
        zbuf[i] = fmaf(qs, eps[gi], qm);
        qmB[i] = qm;
        v1B[i] = fmaf(qs, qs, qm * qm);
    }
    __syncthreads();

    // ================= Stage 1: mean GEMM + log_px accumulation ==============
    float px = 0.f;  // sum of (x-mean)^2 over this thread's elements
    {
        const int g = tid >> 4;    // 0..15 row-group (2 rows each)
        const int t = tid & 15;    // 0..15 col lane
        const int r0 = 2 * g, r1 = r0 + 1;
        const float4* z0p = (const float4*)(zbuf + r0 * ZD);
        const float4* z1p = (const float4*)(zbuf + r1 * ZD);

        for (int tl = 0; tl < NTILE; tl++) {
            const int off = tl * TILE;
            // load W tile transposed: Wt2[c][z] = W[z][off+c]
            for (int i = tid; i < ZD * TILE; i += THREADS) {
                int z = i / TILE;
                int c = i - z * TILE;
                Wt2[c * SP + z] = W[z * XD + off + c];
            }
            if (tid < TILE) bt[tid] = bdec[off + tid];
            __syncthreads();

            float a0[7], a1[7];
#pragma unroll
            for (int j = 0; j < 7; j++) {
                float bb = bt[t + 16 * j];
                a0[j] = bb;
                a1[j] = bb;
            }
#pragma unroll 4
            for (int z4 = 0; z4 < 16; z4++) {
                float4 za = z0p[z4];
                float4 zb = z1p[z4];
#pragma unroll
                for (int j = 0; j < 7; j++) {
                    float4 w = *(const float4*)(Wt2 + (t + 16 * j) * SP + 4 * z4);
                    a0[j] = fmaf(za.x, w.x, a0[j]);
                    a0[j] = fmaf(za.y, w.y, a0[j]);
                    a0[j] = fmaf(za.z, w.z, a0[j]);
                    a0[j] = fmaf(za.w, w.w, a0[j]);
                    a1[j] = fmaf(zb.x, w.x, a1[j]);
                    a1[j] = fmaf(zb.y, w.y, a1[j]);
                    a1[j] = fmaf(zb.z, w.z, a1[j]);
                    a1[j] = fmaf(zb.w, w.w, a1[j]);
                }
            }
#pragma unroll
            for (int j = 0; j < 7; j++) {
                int c = off + t + 16 * j;
                float d0 = x[(rowbase + r0) * XD + c] - a0[j];
                float d1 = x[(rowbase + r1) * XD + c] - a1[j];
                px = fmaf(d0, d0, px);
                px = fmaf(d1, d1, px);
            }
            __syncthreads();  // before Wt2 is overwritten (or reused as compS)
        }
    }

    // ================= Stage 2a: per-(row,k) quadratics =======================
    {
        const int kq = tid & 63;
        const int rq = tid >> 6;  // warp-uniform
        const float cc = g_cc2[kq];
        const float ck = g_ck2[kq];
        const float4* sp4 = (const float4*)(s2 + kq * SP);
        const float4* ap4 = (const float4*)(na2 + kq * SP);
        for (int i = 0; i < ROWS / 4; i++) {
            const int r = rq + 4 * i;
            const float4* zp = (const float4*)(zbuf + r * ZD);
            const float4* qp = (const float4*)(qmB + r * ZD);
            const float4* vp = (const float4*)(v1B + r * ZD);
            float accC = 0.f, accK = 0.f;
#pragma unroll 4
            for (int z4 = 0; z4 < 16; z4++) {
                float4 s = sp4[z4];
                float4 a = ap4[z4];
                float4 zz = zp[z4];
                float4 qm = qp[z4];
                float4 v1 = vp[z4];
                float t0;
                t0 = fmaf(s.x, zz.x, a.x); accC = fmaf(t0, zz.x, accC);
                t0 = fmaf(s.y, zz.y, a.y); accC = fmaf(t0, zz.y, accC);
                t0 = fmaf(s.z, zz.z, a.z); accC = fmaf(t0, zz.z, accC);
                t0 = fmaf(s.w, zz.w, a.w); accC = fmaf(t0, zz.w, accC);
                accK = fmaf(s.x, v1.x, accK); accK = fmaf(a.x, qm.x, accK);
                accK = fmaf(s.y, v1.y, accK); accK = fmaf(a.y, qm.y, accK);
                accK = fmaf(s.z, v1.z, accK); accK = fmaf(a.z, qm.z, accK);
                accK = fmaf(s.w, v1.w, accK); accK = fmaf(a.w, qm.w, accK);
            }
            compS[r * KK + kq] = fmaf(-0.5f, accC, cc);
            klzS[r * KK + kq] = fmaf(0.5f, accK, ck);
        }
    }
    __syncthreads();

    // ================= Stage 2b: softmax / KL per row (warp per row) =========
    float kl_acc = 0.f;  // meaningful on lane 0 only
    {
        const int warp = tid >> 5, lane = tid & 31;
        for (int rr = 0; rr < ROWS / 8; rr++) {
            const int r = warp + 8 * rr;
            const int grow = rowbase + r;
            float c0 = compS[r * KK + lane];
            float c1 = compS[r * KK + lane + 32];
            float k0 = klzS[r * KK + lane];
            float k1 = klzS[r * KK + lane + 32];
            float lp0 = logf(pi[grow * KK + lane]);
            float lp1 = logf(pi[grow * KK + lane + 32]);
            float q0 = qls[grow * ZD + lane];
            float q1 = qls[grow * ZD + lane + 32];

            float qsum = q0 + q1;
#pragma unroll
            for (int o = 16; o; o >>= 1) qsum += __shfl_xor_sync(~0u, qsum, o);

            float p0 = c0 + lp0, p1 = c1 + lp1;
            float m = fmaxf(p0, p1);
#pragma unroll
            for (int o = 16; o; o >>= 1) m = fmaxf(m, __shfl_xor_sync(~0u, m, o));
            float e0 = expf(p0 - m), e1 = expf(p1 - m);
            float es = e0 + e1;
#pragma unroll
            for (int o = 16; o; o >>= 1) es += __shfl_xor_sync(~0u, es, o);
            float lse = m + logf(es);
            float inv = 1.f / es;
            float pr0 = e0 * inv, pr1 = e1 * inv;

            float klf0 = k0 - qsum - 32.f;
            float klf1 = k1 - qsum - 32.f;
            float contrib = pr0 * (c0 - lse) + pr1 * (c1 - lse)
                          + pr0 * klf0 + pr1 * klf1;   // kl_y + kl_z for this row
#pragma unroll
            for (int o = 16; o; o >>= 1) contrib += __shfl_xor_sync(~0u, contrib, o);
            if (lane == 0) kl_acc += contrib;
        }

        // ---- deterministic block reduction ----
        float pxw = px;
#pragma unroll
        for (int o = 16; o; o >>= 1) pxw += __shfl_xor_sync(~0u, pxw, o);
        if (lane == 0) {
            red[warp] = pxw;
            red[8 + warp] = kl_acc;
        }
    }
    __syncthreads();
    if (tid == 0) {
        float sp_ = 0.f, sk = 0.f;
#pragma unroll
        for (int w = 0; w < 8; w++) {
            sp_ += red[w];
            sk += red[8 + w];
        }
        g_part[blockIdx.x] = -0.5f * sp_ - sk;
    }
}

__global__ void final_kernel(float* __restrict__ out) {
    __shared__ float sh[256];
    int tid = threadIdx.x;
    sh[tid] = g_part[tid] + g_part[tid + 256];
    __syncthreads();
    for (int s = 128; s; s >>= 1) {
        if (tid < s) sh[tid] += sh[tid + s];
        __syncthreads();
    }
    if (tid == 0)
        out[0] = sh[0] * (1.f / 16384.f) + (float)(-0.5 * LOG2PI * (double)XD);
}

extern "C" void kernel_launch(void* const* d_in, const int* in_sizes, int n_in,
                              void* d_out, int out_size) {
    (void)in_sizes; (void)n_in; (void)out_size;
    const float* x    = (const float*)d_in[0];
    const float* pi   = (const float*)d_in[1];
    const float* qmu  = (const float*)d_in[2];
    const float* qls  = (const float*)d_in[3];
    const float* eps  = (const float*)d_in[4];
    const float* pmu  = (const float*)d_in[5];
    const float* pls  = (const float*)d_in[6];
    const float* W    = (const float*)d_in[7];
    const float* bdec = (const float*)d_in[8];

    cudaFuncSetAttribute(main_kernel, cudaFuncAttributeMaxDynamicSharedMemorySize,
                         SMEM_BYTES);
    precomp_kernel<<<1, 64>>>(pmu, pls);
    main_kernel<<<NBLK, THREADS, SMEM_BYTES>>>(x, pi, qmu, qls, eps, W, bdec);
    final_kernel<<<1, 256>>>((float*)d_out);
}

// round 2
// speedup vs baseline: 1.3436x; 1.3436x over previous
#include <cuda_runtime.h>

// GMMVAE ELBO, fully fused, f32x2-packed math. B=16384, X=784, Z=K=64.
typedef unsigned long long ull;

#define B_TOT 16384
#define XD 784
#define ZD 64
#define KK 64
#define ROWS 64
#define THREADS 256
#define NBLK (B_TOT / ROWS)   // 256
#define TILE 112
#define NTILE 7
#define ZTP 66                // zT row stride (even -> 8B aligned, 2-way max on store)
#define LOG2PI 1.8378770664093453

__device__ float g_s2inv[KK * ZD];
__device__ float g_na2[KK * ZD];
__device__ float g_cc2[KK];
__device__ float g_ck2[KK];
__device__ float g_part[NBLK];

// smem (floats):
//  zbuf [64][64]            4096
//  zT   [64][66] -> qmB     4224
//  U1: Ws[7168]+bt[112] | s2sw[4096]+na2sw[4096]   8192
//  U2: v1B 4096 + compS 4096 + klzS 4096          12288
//  red 16
#define SMEM_FLOATS (4096 + 4224 + 8192 + 12288 + 16)
#define SMEM_BYTES (SMEM_FLOATS * 4)

// ---------- f32x2 helpers ----------
__device__ __forceinline__ ull fma2o(ull a, ull b, ull c) {
    ull d;
    asm("fma.rn.f32x2 %0, %1, %2, %3;" : "=l"(d) : "l"(a), "l"(b), "l"(c));
    return d;
}
__device__ __forceinline__ ull dup2(float x) {
    ull r;
    asm("mov.b64 %0, {%1, %1};" : "=l"(r) : "f"(x));
    return r;
}
__device__ __forceinline__ void unpack2(ull v, float& lo, float& hi) {
    asm("mov.b64 {%0, %1}, %2;" : "=f"(lo), "=f"(hi) : "l"(v));
}

__global__ void precomp_kernel(const float* __restrict__ pmu,
                               const float* __restrict__ pls) {
    const int k = blockIdx.x;
    const int z = threadIdx.x;
    __shared__ float sh[4];
    float ls = pls[k * ZD + z];
    float mu = pmu[k * ZD + z];
    float s2i = expf(-2.f * ls);
    g_s2inv[k * ZD + z] = s2i;
    g_na2[k * ZD + z] = -2.f * mu * s2i;
    float c1 = mu * mu * s2i;
    float l = ls;
#pragma unroll
    for (int o = 16; o; o >>= 1) {
        c1 += __shfl_xor_sync(~0u, c1, o);
        l += __shfl_xor_sync(~0u, l, o);
    }
    const int w = z >> 5;
    if ((z & 31) == 0) { sh[w] = l; sh[2 + w] = c1; }
    __syncthreads();
    if (z == 0) {
        float lsum = sh[0] + sh[1];
        float cs = sh[2] + sh[3];
        g_cc2[k] = (float)(-(double)lsum - 32.0 * LOG2PI - 0.5 * (double)cs);
        g_ck2[k] = lsum + 0.5f * cs;
    }
}

extern __shared__ float smem[];

__global__ __launch_bounds__(THREADS, 2)
void main_kernel(const float* __restrict__ x, const float* __restrict__ pi,
                 const float* __restrict__ qmu, const float* __restrict__ qls,
                 const float* __restrict__ eps, const float* __restrict__ W,
                 const float* __restrict__ bdec) {
    float* zbuf = smem;                  // [64][64]
    float* zT = zbuf + ROWS * ZD;        // [64][66]; later qmB[64][64]
    float* qmB = zT;
    float* U1 = zT + ZD * ZTP;
    float* Ws = U1;                      // [64][112]
    float* bt = U1 + ZD * TILE;          // [112]
    float* s2sw = U1;                    // [64][64] swizzled
    float* na2sw = U1 + KK * ZD;
    float* U2 = U1 + 8192;
    float* v1B = U2;                     // [64][64]
    float* compS = U2 + ROWS * ZD;       // [64][64]
    float* klzS = compS + ROWS * KK;     // [64][64]
    float* red = klzS + ROWS * KK;       // [16]

    const int tid = threadIdx.x;
    const int rowbase = blockIdx.x * ROWS;

    // ---- init: z values -> zbuf (row-major) and zT (transposed) ----
    for (int i = tid; i < ROWS * ZD; i += THREADS) {
        const int r = i >> 6, zz = i & 63;
        const int gi = (rowbase + r) * ZD + zz;
        float qm = qmu[gi];
        float qs = expf(qls[gi]);
        float zv = fmaf(qs, eps[gi], qm);
        zbuf[i] = zv;
        zT[zz * ZTP + r] = zv;
    }
    __syncthreads();

    // ================= Stage 1: mean GEMM + log_px ==============
    float px = 0.f;
    {
        const int cg = tid & 7;      // 8 col groups x 14 cols
        const int rg = tid >> 3;     // 32 row groups x 2 rows
        const int c0 = 14 * cg;
        const float4* Wg4 = (const float4*)W;

        for (int tl = 0; tl < NTILE; tl++) {
            const int off = TILE * tl;
            const int off4 = off >> 2;
            float4* Ws4 = (float4*)Ws;
#pragma unroll
            for (int i = tid; i < (ZD * TILE) / 4; i += THREADS) {
                const int zz = i / 28, c4 = i - zz * 28;
                Ws4[i] = Wg4[zz * (XD / 4) + off4 + c4];
            }
            if (tid < TILE) bt[tid] = bdec[off + tid];
            __syncthreads();

            ull acc0[7], acc1[7];
#pragma unroll
            for (int p = 0; p < 7; p++) {
                ull b = *(const ull*)(bt + c0 + 2 * p);
                acc0[p] = b;
                acc1[p] = b;
            }
            const float* wz = Ws + c0;
            const float* zt = zT + 2 * rg;
#pragma unroll 4
            for (int zz = 0; zz < ZD; zz++) {
                float2 zp = *(const float2*)(zt + zz * ZTP);
                ull a0 = dup2(zp.x);
                ull a1 = dup2(zp.y);
                const ull* w2 = (const ull*)(wz + zz * TILE);
#pragma unroll
                for (int p = 0; p < 7; p++) {
                    ull w = w2[p];
                    acc0[p] = fma2o(a0, w, acc0[p]);
                    acc1[p] = fma2o(a1, w, acc1[p]);
                }
            }
            const float* xr0 = x + (rowbase + 2 * rg) * XD + off + c0;
            const float* xr1 = xr0 + XD;
#pragma unroll
            for (int p = 0; p < 7; p++) {
                float2 xv0 = *(const float2*)(xr0 + 2 * p);
                float2 xv1 = *(const float2*)(xr1 + 2 * p);
                float lo, hi;
                unpack2(acc0[p], lo, hi);
                float d0 = xv0.x - lo, d1 = xv0.y - hi;
                px = fmaf(d0, d0, px);
                px = fmaf(d1, d1, px);
                unpack2(acc1[p], lo, hi);
                d0 = xv1.x - lo; d1 = xv1.y - hi;
                px = fmaf(d0, d0, px);
                px = fmaf(d1, d1, px);
            }
            __syncthreads();
        }
    }

    // ---- post-stage1: build qmB (over zT), v1B; load swizzled s2/na2 ----
    for (int i = tid; i < ROWS * ZD; i += THREADS) {
        const int gi = (rowbase + (i >> 6)) * ZD + (i & 63);
        float qm = qmu[gi];
        float qs = expf(qls[gi]);
        qmB[i] = qm;
        v1B[i] = fmaf(qs, qs, qm * qm);
    }
    for (int i = tid; i < KK * ZD; i += THREADS) {
        const int k = i >> 6, zz = i & 63;
        const int ph = k * ZD + 4 * ((zz >> 2) ^ (k & 15)) + (zz & 3);
        s2sw[ph] = g_s2inv[i];
        na2sw[ph] = g_na2[i];
    }
    __syncthreads();

    // ================= Stage 2a: per-(row,k) quadratics (f32x2) ==========
    {
        const int k = tid & 63;
        const int rg = tid >> 6;  // 0..3
        const int kx = k & 15;
        const float cc = g_cc2[k];
        const float ck = g_ck2[k];
        const float* sbase = s2sw + k * ZD;
        const float* abase = na2sw + k * ZD;
#pragma unroll
        for (int pass = 0; pass < 2; pass++) {
            const int r0 = rg * 16 + pass * 8;
            ull accC[8], accK[8];
#pragma unroll
            for (int i = 0; i < 8; i++) { accC[i] = 0ull; accK[i] = 0ull; }
            for (int z4 = 0; z4 < 16; z4++) {
                const int sl = 4 * (z4 ^ kx);
                ulonglong2 sv = *(const ulonglong2*)(sbase + sl);
                ulonglong2 av = *(const ulonglong2*)(abase + sl);
#pragma unroll
                for (int ri = 0; ri < 8; ri++) {
                    const int rb = (r0 + ri) * ZD + 4 * z4;
                    ulonglong2 zv = *(const ulonglong2*)(zbuf + rb);
                    ulonglong2 qv = *(const ulonglong2*)(qmB + rb);
                    ulonglong2 vv = *(const ulonglong2*)(v1B + rb);
                    ull t;
                    t = fma2o(sv.x, zv.x, av.x);
                    accC[ri] = fma2o(t, zv.x, accC[ri]);
                    t = fma2o(sv.y, zv.y, av.y);
                    accC[ri] = fma2o(t, zv.y, accC[ri]);
                    accK[ri] = fma2o(sv.x, vv.x, accK[ri]);
                    accK[ri] = fma2o(av.x, qv.x, accK[ri]);
                    accK[ri] = fma2o(sv.y, vv.y, accK[ri]);
                    accK[ri] = fma2o(av.y, qv.y, accK[ri]);
                }
            }
#pragma unroll
            for (int ri = 0; ri < 8; ri++) {
                float lo, hi;
                unpack2(accC[ri], lo, hi);
                compS[(r0 + ri) * KK + k] = fmaf(-0.5f, lo + hi, cc);
                unpack2(accK[ri], lo, hi);
                klzS[(r0 + ri) * KK + k] = fmaf(0.5f, lo + hi, ck);
            }
        }
    }
    __syncthreads();

    // ================= Stage 2b: softmax / KL (warp per row) =========
    float kl_acc = 0.f;
    {
        const int warp = tid >> 5, lane = tid & 31;
        for (int rr = 0; rr < ROWS / 8; rr++) {
            const int r = warp + 8 * rr;
            const int grow = rowbase + r;
            float c0 = compS[r * KK + lane];
            float c1 = compS[r * KK + lane + 32];
            float k0 = klzS[r * KK + lane];
            float k1 = klzS[r * KK + lane + 32];
            float lp0 = logf(pi[grow * KK + lane]);
            float lp1 = logf(pi[grow * KK + lane + 32]);
            float q0 = qls[grow * ZD + lane];
            float q1 = qls[grow * ZD + lane + 32];

            float qsum = q0 + q1;
#pragma unroll
            for (int o = 16; o; o >>= 1) qsum += __shfl_xor_sync(~0u, qsum, o);

            float p0 = c0 + lp0, p1 = c1 + lp1;
            float m = fmaxf(p0, p1);
#pragma unroll
            for (int o = 16; o; o >>= 1) m = fmaxf(m, __shfl_xor_sync(~0u, m, o));
            float e0 = expf(p0 - m), e1 = expf(p1 - m);
            float es = e0 + e1;
#pragma unroll
            for (int o = 16; o; o >>= 1) es += __shfl_xor_sync(~0u, es, o);
            float lse = m + logf(es);
            float inv = 1.f / es;
            float pr0 = e0 * inv, pr1 = e1 * inv;

            float klf0 = k0 - qsum - 32.f;
            float klf1 = k1 - qsum - 32.f;
            float contrib = pr0 * (c0 - lse) + pr1 * (c1 - lse)
                          + pr0 * klf0 + pr1 * klf1;
#pragma unroll
            for (int o = 16; o; o >>= 1) contrib += __shfl_xor_sync(~0u, contrib, o);
            if (lane == 0) kl_acc += contrib;
        }

        float pxw = px;
#pragma unroll
        for (int o = 16; o; o >>= 1) pxw += __shfl_xor_sync(~0u, pxw, o);
        if (lane == 0) {
            red[warp] = pxw;
            red[8 + warp] = kl_acc;
        }
    }
    __syncthreads();
    if (tid == 0) {
        float sp_ = 0.f, sk = 0.f;
#pragma unroll
        for (int w = 0; w < 8; w++) {
            sp_ += red[w];
            sk += red[8 + w];
        }
        g_part[blockIdx.x] = -0.5f * sp_ - sk;
    }
}

__global__ void final_kernel(float* __restrict__ out) {
    __shared__ float sh[256];
    const int tid = threadIdx.x;
    sh[tid] = g_part[tid];
    __syncthreads();
    for (int s = 128; s; s >>= 1) {
        if (tid < s) sh[tid] += sh[tid + s];
        __syncthreads();
    }
    if (tid == 0)
        out[0] = sh[0] * (1.f / 16384.f) + (float)(-0.5 * LOG2PI * (double)XD);
}

extern "C" void kernel_launch(void* const* d_in, const int* in_sizes, int n_in,
                              void* d_out, int out_size) {
    (void)in_sizes; (void)n_in; (void)out_size;
    const float* x    = (const float*)d_in[0];
    const float* pi   = (const float*)d_in[1];
    const float* qmu  = (const float*)d_in[2];
    const float* qls  = (const float*)d_in[3];
    const float* eps  = (const float*)d_in[4];
    const float* pmu  = (const float*)d_in[5];
    const float* pls  = (const float*)d_in[6];
    const float* W    = (const float*)d_in[7];
    const float* bdec = (const float*)d_in[8];

    cudaFuncSetAttribute(main_kernel, cudaFuncAttributeMaxDynamicSharedMemorySize,
                         SMEM_BYTES);
    precomp_kernel<<<KK, ZD>>>(pmu, pls);
    main_kernel<<<NBLK, THREADS, SMEM_BYTES>>>(x, pi, qmu, qls, eps, W, bdec);
    final_kernel<<<1, 256>>>((float*)d_out);
}

// round 4
// speedup vs baseline: 2.5721x; 1.9143x over previous
#include <cuda_runtime.h>
#include <cuda_bf16.h>
#include <cstdint>

// GMMVAE ELBO. Stage1 via mma.sync bf16 (base ISA tensor cores), stage2 f32x2.
typedef unsigned long long ull;

#define B_TOT 16384
#define XD 784
#define ZD 64
#define KK 64
#define ROWS 128
#define THREADS 256
#define NBLK (B_TOT / ROWS)   // 128
#define NTILES 98             // 784 / 8
#define ZSTR 72               // bf16 element stride (144B rows) for mma operands
#define RSTR 65               // f32 row-array stride (stage 2)
#define LOG2PI 1.8378770664093453

__device__ float g_s2T[ZD * KK];   // [z][k]
__device__ float g_na2T[ZD * KK];  // [z][k]
__device__ float g_cc2[KK];
__device__ float g_ck2[KK];
__device__ float g_part[NBLK];
__device__ __align__(16) __nv_bfloat16 g_Wt[XD * ZSTR];  // [c][z] stride 72

// ---- smem byte offsets ----
#define OFF_RED   0        // red[16] floats
#define OFF_BIAS  128      // 784 f32 -> ends 3264
#define OFF_ZBF   3328     // 128*72*2 = 18432 -> 21760
#define OFF_WT    21760    // 784*72*2 = 112896 -> 134656
// overlay after stage1 (reuses ZBF+WT region):
#define OFF_ZR    21760    // [128][65] f32 = 33280 -> 55040
#define OFF_V1    55040    // 33280 -> 88320
#define OFF_QM    88320    // 33280 -> 121600
#define OFF_S2T   121600   // 64*64*4 = 16384 -> 137984
#define OFF_NA2T  137984   // 16384 -> 154368
#define OFF_COMP  154368   // 128*64*4 = 32768 -> 187136
#define OFF_KLZ   187136   // 32768 -> 219904
#define SMEM_BYTES 219904

__device__ __forceinline__ uint32_t smem_u32(const void* p) {
    uint32_t a;
    asm("{ .reg .u64 t; cvta.to.shared.u64 t, %1; cvt.u32.u64 %0, t; }" : "=r"(a) : "l"(p));
    return a;
}
__device__ __forceinline__ ull fma2o(ull a, ull b, ull c) {
    ull d;
    asm("fma.rn.f32x2 %0, %1, %2, %3;" : "=l"(d) : "l"(a), "l"(b), "l"(c));
    return d;
}
__device__ __forceinline__ ull dup2(float x) {
    ull r;
    asm("mov.b64 %0, {%1, %1};" : "=l"(r) : "f"(x));
    return r;
}
__device__ __forceinline__ void unpack2(ull v, float& lo, float& hi) {
    asm("mov.b64 {%0, %1}, %2;" : "=f"(lo), "=f"(hi) : "l"(v));
}
__device__ __forceinline__ void ldm_x4(uint32_t& r0, uint32_t& r1, uint32_t& r2,
                                       uint32_t& r3, uint32_t addr) {
    asm volatile("ldmatrix.sync.aligned.m8n8.x4.shared.b16 {%0,%1,%2,%3}, [%4];"
                 : "=r"(r0), "=r"(r1), "=r"(r2), "=r"(r3) : "r"(addr));
}
__device__ __forceinline__ void mma_bf16(float& c0, float& c1, float& c2, float& c3,
                                         uint32_t a0, uint32_t a1, uint32_t a2, uint32_t a3,
                                         uint32_t b0, uint32_t b1) {
    asm volatile("mma.sync.aligned.m16n8k16.row.col.f32.bf16.bf16.f32 "
                 "{%0,%1,%2,%3}, {%4,%5,%6,%7}, {%8,%9}, {%0,%1,%2,%3};"
                 : "+f"(c0), "+f"(c1), "+f"(c2), "+f"(c3)
                 : "r"(a0), "r"(a1), "r"(a2), "r"(a3), "r"(b0), "r"(b1));
}

// ======================= prep kernel (grid 8) =======================
// blocks 0..6: transpose W[64][784] -> g_Wt[c][z] bf16, 112 cols per block
// block 7: per-k constants (threads 0..63), written transposed [z][k]
__global__ void prep_kernel(const float* __restrict__ W,
                            const float* __restrict__ pmu,
                            const float* __restrict__ pls) {
    const int b = blockIdx.x, tid = threadIdx.x;
    if (b < 7) {
        for (int idx = tid; idx < 112 * ZD; idx += 256) {
            const int z = idx / 112, nl = idx - z * 112;
            const int c = b * 112 + nl;
            g_Wt[c * ZSTR + z] = __float2bfloat16(W[z * XD + c]);
        }
    } else if (tid < KK) {
        const int k = tid;
        float lsum = 0.f, c1 = 0.f;
        for (int z = 0; z < ZD; z++) {
            float ls = pls[k * ZD + z];
            float mu = pmu[k * ZD + z];
            float s2i = expf(-2.f * ls);
            g_s2T[z * KK + k] = s2i;
            g_na2T[z * KK + k] = -2.f * mu * s2i;
            lsum += ls;
            c1 = fmaf(mu * mu, s2i, c1);
        }
        g_cc2[k] = (float)(-(double)lsum - 32.0 * LOG2PI - 0.5 * (double)c1);
        g_ck2[k] = lsum + 0.5f * c1;
    }
}

// ======================= main kernel =======================
extern __shared__ char smem[];

__global__ __launch_bounds__(THREADS, 1)
void main_kernel(const float* __restrict__ x, const float* __restrict__ pi,
                 const float* __restrict__ qmu, const float* __restrict__ qls,
                 const float* __restrict__ eps, const float* __restrict__ bdec) {
    const int tid = threadIdx.x;
    const int wid = tid >> 5, lane = tid & 31;
    const int rowbase = blockIdx.x * ROWS;
    const uint32_t sbase = smem_u32(smem);
    float* red = (float*)(smem + OFF_RED);
    float* biasS = (float*)(smem + OFF_BIAS);

    // ---- load Wt into smem (contiguous bf16 image) ----
    {
        const uint4* src = (const uint4*)g_Wt;
        uint4* dst = (uint4*)(smem + OFF_WT);
        for (int i = tid; i < (XD * ZSTR * 2) / 16; i += THREADS) dst[i] = src[i];
    }
    for (int i = tid; i < XD; i += THREADS) biasS[i] = bdec[i];

    // ---- build z (bf16, stride 72) ----
    for (int i = tid; i < ROWS * 32; i += THREADS) {
        const int r = i >> 5, zp = i & 31;
        const int gi = (rowbase + r) * ZD + 2 * zp;
        float2 qm2 = *(const float2*)(qmu + gi);
        float2 ql2 = *(const float2*)(qls + gi);
        float2 ep2 = *(const float2*)(eps + gi);
        float z0 = fmaf(expf(ql2.x), ep2.x, qm2.x);
        float z1 = fmaf(expf(ql2.y), ep2.y, qm2.y);
        __nv_bfloat162 bv = __floats2bfloat162_rn(z0, z1);
        *(uint32_t*)(smem + OFF_ZBF + (r * ZSTR + 2 * zp) * 2) = *(uint32_t*)&bv;
    }
    __syncthreads();

    // ================= Stage 1: mean GEMM (mma.sync) + log_px ==============
    float px = 0.f;
    {
        const int g = lane >> 3, lr = lane & 7;
        // A fragments: rows 16*wid..+15, full K=64
        uint32_t a[16];
        {
            const uint32_t aaddr = sbase + OFF_ZBF
                + (16 * wid + lr + 8 * (g & 1)) * (ZSTR * 2) + (8 * (g >> 1)) * 2;
#pragma unroll
            for (int kt = 0; kt < 4; kt++)
                ldm_x4(a[4 * kt], a[4 * kt + 1], a[4 * kt + 2], a[4 * kt + 3],
                       aaddr + kt * 32);
        }
        const uint32_t baddr0 = sbase + OFF_WT + lr * (ZSTR * 2) + (8 * g) * 2;
        const float* pxA = x + (size_t)(rowbase + 16 * wid + (lane >> 2)) * XD + 2 * (lane & 3);
        const float* pxB = pxA + 8 * XD;
        const float* bP = biasS + 2 * (lane & 3);

#pragma unroll 2
        for (int j = 0; j < NTILES; j++) {
            uint32_t b[8];
            const uint32_t ba = baddr0 + j * (8 * ZSTR * 2);
            ldm_x4(b[0], b[1], b[2], b[3], ba);
            ldm_x4(b[4], b[5], b[6], b[7], ba + 64);
            float c0 = 0.f, c1 = 0.f, c2 = 0.f, c3 = 0.f;
            mma_bf16(c0, c1, c2, c3, a[0], a[1], a[2], a[3], b[0], b[1]);
            mma_bf16(c0, c1, c2, c3, a[4], a[5], a[6], a[7], b[2], b[3]);
            mma_bf16(c0, c1, c2, c3, a[8], a[9], a[10], a[11], b[4], b[5]);
            mma_bf16(c0, c1, c2, c3, a[12], a[13], a[14], a[15], b[6], b[7]);

            float2 bb = *(const float2*)(bP + 8 * j);
            float2 xa = *(const float2*)(pxA + 8 * j);
            float2 xb = *(const float2*)(pxB + 8 * j);
            float d;
            d = (xa.x - bb.x) - c0; px = fmaf(d, d, px);
            d = (xa.y - bb.y) - c1; px = fmaf(d, d, px);
            d = (xb.x - bb.x) - c2; px = fmaf(d, d, px);
            d = (xb.y - bb.y) - c3; px = fmaf(d, d, px);
        }
    }
    __syncthreads();

    // ---- build stage-2 arrays (overlay Wt/zbf region) ----
    float* zR = (float*)(smem + OFF_ZR);
    float* v1S = (float*)(smem + OFF_V1);
    float* qmS = (float*)(smem + OFF_QM);
    float* s2T = (float*)(smem + OFF_S2T);
    float* na2T = (float*)(smem + OFF_NA2T);
    float* compS = (float*)(smem + OFF_COMP);
    float* klzS = (float*)(smem + OFF_KLZ);

    {
        const uint4* s1 = (const uint4*)g_s2T;
        const uint4* s2 = (const uint4*)g_na2T;
        uint4* d1 = (uint4*)s2T;
        uint4* d2 = (uint4*)na2T;
        for (int i = tid; i < (ZD * KK) / 4; i += THREADS) {
            d1[i] = s1[i];
            d2[i] = s2[i];
        }
    }
    for (int i = tid; i < ROWS * ZD; i += THREADS) {
        const int r = i >> 6, z = i & 63;
        const int gi = (rowbase + r) * ZD + z;
        float qm = qmu[gi];
        float qs = expf(qls[gi]);
        zR[r * RSTR + z] = fmaf(qs, eps[gi], qm);
        v1S[r * RSTR + z] = fmaf(qs, qs, qm * qm);
        qmS[r * RSTR + z] = qm;
    }
    __syncthreads();

    // ================= Stage 2a: quadratics, tile 4r x 8k per thread =========
    {
        const int tx = tid & 7, ty = tid >> 3;
        const int kb = 8 * tx, r0 = 4 * ty;
        ull accC[4][4], accK[4][4];
#pragma unroll
        for (int r = 0; r < 4; r++)
#pragma unroll
            for (int k = 0; k < 4; k++) { accC[r][k] = 0ull; accK[r][k] = 0ull; }

        const float* s2p = s2T + kb;
        const float* nap = na2T + kb;
#pragma unroll 4
        for (int z = 0; z < ZD; z++) {
            ulonglong2 sA = *(const ulonglong2*)(s2p + z * KK);
            ulonglong2 sB = *(const ulonglong2*)(s2p + z * KK + 4);
            ulonglong2 nA = *(const ulonglong2*)(nap + z * KK);
            ulonglong2 nB = *(const ulonglong2*)(nap + z * KK + 4);
#pragma unroll
            for (int r = 0; r < 4; r++) {
                const int rb = (r0 + r) * RSTR + z;
                ull zd = dup2(zR[rb]);
                ull vd = dup2(v1S[rb]);
                ull qd = dup2(qmS[rb]);
                ull t;
                t = fma2o(sA.x, zd, nA.x); accC[r][0] = fma2o(t, zd, accC[r][0]);
                t = fma2o(sA.y, zd, nA.y); accC[r][1] = fma2o(t, zd, accC[r][1]);
                t = fma2o(sB.x, zd, nB.x); accC[r][2] = fma2o(t, zd, accC[r][2]);
                t = fma2o(sB.y, zd, nB.y); accC[r][3] = fma2o(t, zd, accC[r][3]);
                accK[r][0] = fma2o(sA.x, vd, accK[r][0]);
                accK[r][0] = fma2o(nA.x, qd, accK[r][0]);
                accK[r][1] = fma2o(sA.y, vd, accK[r][1]);
                accK[r][1] = fma2o(nA.y, qd, accK[r][1]);
                accK[r][2] = fma2o(sB.x, vd, accK[r][2]);
                accK[r][2] = fma2o(nB.x, qd, accK[r][2]);
                accK[r][3] = fma2o(sB.y, vd, accK[r][3]);
                accK[r][3] = fma2o(nB.y, qd, accK[r][3]);
            }
        }
        float cc[8], ck[8];
        *(float4*)cc = *(const float4*)(g_cc2 + kb);
        *(float4*)(cc + 4) = *(const float4*)(g_cc2 + kb + 4);
        *(float4*)ck = *(const float4*)(g_ck2 + kb);
        *(float4*)(ck + 4) = *(const float4*)(g_ck2 + kb + 4);
#pragma unroll
        for (int r = 0; r < 4; r++) {
#pragma unroll
            for (int k = 0; k < 4; k++) {
                float lo, hi;
                unpack2(accC[r][k], lo, hi);
                *(float2*)(compS + (r0 + r) * KK + kb + 2 * k) =
                    make_float2(fmaf(-0.5f, lo, cc[2 * k]), fmaf(-0.5f, hi, cc[2 * k + 1]));
                unpack2(accK[r][k], lo, hi);
                *(float2*)(klzS + (r0 + r) * KK + kb + 2 * k) =
                    make_float2(fmaf(0.5f, lo, ck[2 * k]), fmaf(0.5f, hi, ck[2 * k + 1]));
            }
        }
    }
    __syncthreads();

    // ================= Stage 2b: softmax / KL (warp per row) =========
    float kl_acc = 0.f;
    for (int rr = 0; rr < 16; rr++) {
        const int r = wid + 8 * rr;
        const int grow = rowbase + r;
        float c0 = compS[r * KK + lane];
        float c1 = compS[r * KK + lane + 32];
        float k0 = klzS[r * KK + lane];
        float k1 = klzS[r * KK + lane + 32];
        float lp0 = logf(pi[grow * KK + lane]);
        float lp1 = logf(pi[grow * KK + lane + 32]);
        float q0 = qls[grow * ZD + lane];
        float q1 = qls[grow * ZD + lane + 32];

        float qsum = q0 + q1;
#pragma unroll
        for (int o = 16; o; o >>= 1) qsum += __shfl_xor_sync(~0u, qsum, o);
        float p0 = c0 + lp0, p1 = c1 + lp1;
        float m = fmaxf(p0, p1);
#pragma unroll
        for (int o = 16; o; o >>= 1) m = fmaxf(m, __shfl_xor_sync(~0u, m, o));
        float e0 = expf(p0 - m), e1 = expf(p1 - m);
        float es = e0 + e1;
#pragma unroll
        for (int o = 16; o; o >>= 1) es += __shfl_xor_sync(~0u, es, o);
        float lse = m + logf(es);
        float inv = 1.f / es;
        float pr0 = e0 * inv, pr1 = e1 * inv;
        float contrib = pr0 * (c0 - lse) + pr1 * (c1 - lse)
                      + pr0 * (k0 - qsum - 32.f) + pr1 * (k1 - qsum - 32.f);
#pragma unroll
        for (int o = 16; o; o >>= 1) contrib += __shfl_xor_sync(~0u, contrib, o);
        if (lane == 0) kl_acc += contrib;
    }

    // ---- deterministic reductions ----
    float pxw = px;
#pragma unroll
    for (int o = 16; o; o >>= 1) pxw += __shfl_xor_sync(~0u, pxw, o);
    if (lane == 0) { red[wid] = pxw; red[8 + wid] = kl_acc; }
    __syncthreads();
    if (tid == 0) {
        float sp = 0.f, sk = 0.f;
#pragma unroll
        for (int w = 0; w < 8; w++) { sp += red[w]; sk += red[8 + w]; }
        g_part[blockIdx.x] = -0.5f * sp - sk;
    }
}

__global__ void final_kernel(float* __restrict__ out) {
    __shared__ float sh[NBLK];
    const int tid = threadIdx.x;
    sh[tid] = g_part[tid];
    __syncthreads();
    for (int s = NBLK / 2; s; s >>= 1) {
        if (tid < s) sh[tid] += sh[tid + s];
        __syncthreads();
    }
    if (tid == 0)
        out[0] = sh[0] * (1.f / 16384.f) + (float)(-0.5 * LOG2PI * (double)XD);
}

extern "C" void kernel_launch(void* const* d_in, const int* in_sizes, int n_in,
                              void* d_out, int out_size) {
    (void)in_sizes; (void)n_in; (void)out_size;
    const float* x    = (const float*)d_in[0];
    const float* pi   = (const float*)d_in[1];
    const float* qmu  = (const float*)d_in[2];
    const float* qls  = (const float*)d_in[3];
    const float* eps  = (const float*)d_in[4];
    const float* pmu  = (const float*)d_in[5];
    const float* pls  = (const float*)d_in[6];
    const float* W    = (const float*)d_in[7];
    const float* bdec = (const float*)d_in[8];

    cudaFuncSetAttribute(main_kernel, cudaFuncAttributeMaxDynamicSharedMemorySize,
                         SMEM_BYTES);
    prep_kernel<<<8, 256>>>(W, pmu, pls);
    main_kernel<<<NBLK, THREADS, SMEM_BYTES>>>(x, pi, qmu, qls, eps, bdec);
    final_kernel<<<1, NBLK>>>((float*)d_out);
}

// round 5
// speedup vs baseline: 2.9926x; 1.1635x over previous
#include <cuda_runtime.h>
#include <cuda_bf16.h>
#include <cstdint>

// GMMVAE ELBO. Stage1 via mma.sync bf16, stage2 f32x2, single-pass finish.
typedef unsigned long long ull;

#define B_TOT 16384
#define XD 784
#define ZD 64
#define KK 64
#define ROWS 128
#define THREADS 256
#define NBLK (B_TOT / ROWS)   // 128
#define NTILES 98             // 784 / 8
#define ZSTR 72               // bf16 element stride (144B rows) for mma operands
#define RSTR 65               // f32 row-array stride (stage 2)
#define LOG2PI 1.8378770664093453
#define FIXSCALE 262144.0     // 2^18

__device__ float g_s2T[ZD * KK];   // [z][k]
__device__ float g_na2T[ZD * KK];  // [z][k]
__device__ float g_cc2[KK];
__device__ float g_ck2[KK];
__device__ ull g_acc;
__device__ unsigned g_cnt;
__device__ __align__(16) __nv_bfloat16 g_Wt[XD * ZSTR];  // [c][z] stride 72

// ---- smem byte offsets ----
#define OFF_RED   0        // red[16] floats
#define OFF_BIAS  128      // 784 f32 -> ends 3264
#define OFF_ZBF   3328     // 128*72*2 = 18432 -> 21760
#define OFF_WT    21760    // 784*72*2 = 112896 -> 134656
// overlay after stage1:
#define OFF_ZR    21760    // [128][65] f32 = 33280 -> 55040
#define OFF_V1    55040
#define OFF_QM    88320
#define OFF_S2T   121600   // 16384
#define OFF_NA2T  137984   // 16384
#define OFF_COMP  154368   // 32768
#define OFF_KLZ   187136   // 32768 -> 219904
#define SMEM_BYTES 219904

__device__ __forceinline__ uint32_t smem_u32(const void* p) {
    uint32_t a;
    asm("{ .reg .u64 t; cvta.to.shared.u64 t, %1; cvt.u32.u64 %0, t; }" : "=r"(a) : "l"(p));
    return a;
}
__device__ __forceinline__ ull fma2o(ull a, ull b, ull c) {
    ull d;
    asm("fma.rn.f32x2 %0, %1, %2, %3;" : "=l"(d) : "l"(a), "l"(b), "l"(c));
    return d;
}
__device__ __forceinline__ ull dup2(float x) {
    ull r;
    asm("mov.b64 %0, {%1, %1};" : "=l"(r) : "f"(x));
    return r;
}
__device__ __forceinline__ void unpack2(ull v, float& lo, float& hi) {
    asm("mov.b64 {%0, %1}, %2;" : "=f"(lo), "=f"(hi) : "l"(v));
}
__device__ __forceinline__ void ldm_x4(uint32_t& r0, uint32_t& r1, uint32_t& r2,
                                       uint32_t& r3, uint32_t addr) {
    asm volatile("ldmatrix.sync.aligned.m8n8.x4.shared.b16 {%0,%1,%2,%3}, [%4];"
                 : "=r"(r0), "=r"(r1), "=r"(r2), "=r"(r3) : "r"(addr));
}
__device__ __forceinline__ void mma_bf16(float& c0, float& c1, float& c2, float& c3,
                                         uint32_t a0, uint32_t a1, uint32_t a2, uint32_t a3,
                                         uint32_t b0, uint32_t b1) {
    asm volatile("mma.sync.aligned.m16n8k16.row.col.f32.bf16.bf16.f32 "
                 "{%0,%1,%2,%3}, {%4,%5,%6,%7}, {%8,%9}, {%0,%1,%2,%3};"
                 : "+f"(c0), "+f"(c1), "+f"(c2), "+f"(c3)
                 : "r"(a0), "r"(a1), "r"(a2), "r"(a3), "r"(b0), "r"(b1));
}

// ======================= prep kernel (grid 15) =======================
// blocks 0..13: transpose 56 cols each of W[64][784] -> g_Wt[c][z] bf16 (coalesced)
// block 14: per-k constants (4-way split per k + quad shfl reduce) + acc reset
__global__ void prep_kernel(const float* __restrict__ W,
                            const float* __restrict__ pmu,
                            const float* __restrict__ pls) {
    const int b = blockIdx.x, tid = threadIdx.x;
    if (b < 14) {
        __shared__ float sc[64 * 57];
        const int c0 = b * 56;
        for (int i = tid; i < 64 * 56; i += 256) {
            const int z = i / 56, c = i - z * 56;
            sc[z * 57 + c] = W[z * XD + c0 + c];
        }
        __syncthreads();
        for (int i = tid; i < 56 * 32; i += 256) {
            const int c = i >> 5, zp = i & 31;
            __nv_bfloat162 bv = __floats2bfloat162_rn(sc[(2 * zp) * 57 + c],
                                                      sc[(2 * zp + 1) * 57 + c]);
            *(uint32_t*)((char*)g_Wt + (c0 + c) * (ZSTR * 2) + zp * 4) = *(uint32_t*)&bv;
        }
    } else {
        const int k = tid >> 2, q = tid & 3;
        float lsum = 0.f, c1 = 0.f;
#pragma unroll
        for (int i = 0; i < 16; i++) {
            const int z = 16 * q + i;
            float ls = pls[k * ZD + z];
            float mu = pmu[k * ZD + z];
            float s2i = expf(-2.f * ls);
            g_s2T[z * KK + k] = s2i;
            g_na2T[z * KK + k] = -2.f * mu * s2i;
            lsum += ls;
            c1 = fmaf(mu * mu, s2i, c1);
        }
#pragma unroll
        for (int o = 1; o < 4; o <<= 1) {
            lsum += __shfl_xor_sync(~0u, lsum, o);
            c1 += __shfl_xor_sync(~0u, c1, o);
        }
        if (q == 0) {
            g_cc2[k] = (float)(-(double)lsum - 32.0 * LOG2PI - 0.5 * (double)c1);
            g_ck2[k] = lsum + 0.5f * c1;
        }
        if (tid == 0) { g_acc = 0ull; g_cnt = 0u; }
    }
}

// ======================= main kernel =======================
extern __shared__ char smem[];

#define LDB(dst, j) do {                                                       \
    const uint32_t ba_ = baddr0 + (j) * (8 * ZSTR * 2);                        \
    ldm_x4((dst)[0], (dst)[1], (dst)[2], (dst)[3], ba_);                       \
    ldm_x4((dst)[4], (dst)[5], (dst)[6], (dst)[7], ba_ + 64);                  \
} while (0)

#define TILE_BODY(bf, xa, xb, bb) do {                                         \
    float cA0 = 0.f, cA1 = 0.f, cA2 = 0.f, cA3 = 0.f;                          \
    float cB0 = 0.f, cB1 = 0.f, cB2 = 0.f, cB3 = 0.f;                          \
    mma_bf16(cA0, cA1, cA2, cA3, a[0], a[1], a[2], a[3], (bf)[0], (bf)[1]);    \
    mma_bf16(cB0, cB1, cB2, cB3, a[8], a[9], a[10], a[11], (bf)[4], (bf)[5]);  \
    mma_bf16(cA0, cA1, cA2, cA3, a[4], a[5], a[6], a[7], (bf)[2], (bf)[3]);    \
    mma_bf16(cB0, cB1, cB2, cB3, a[12], a[13], a[14], a[15], (bf)[6], (bf)[7]);\
    float d_;                                                                  \
    d_ = ((xa).x - (bb).x) - (cA0 + cB0); px = fmaf(d_, d_, px);               \
    d_ = ((xa).y - (bb).y) - (cA1 + cB1); px = fmaf(d_, d_, px);               \
    d_ = ((xb).x - (bb).x) - (cA2 + cB2); px = fmaf(d_, d_, px);               \
    d_ = ((xb).y - (bb).y) - (cA3 + cB3); px = fmaf(d_, d_, px);               \
} while (0)

__global__ __launch_bounds__(THREADS, 1)
void main_kernel(const float* __restrict__ x, const float* __restrict__ pi,
                 const float* __restrict__ qmu, const float* __restrict__ qls,
                 const float* __restrict__ eps, const float* __restrict__ bdec,
                 float* __restrict__ out) {
    const int tid = threadIdx.x;
    const int wid = tid >> 5, lane = tid & 31;
    const int rowbase = blockIdx.x * ROWS;
    const uint32_t sbase = smem_u32(smem);
    float* red = (float*)(smem + OFF_RED);
    float* biasS = (float*)(smem + OFF_BIAS);

    // ---- load Wt into smem ----
    {
        const uint4* src = (const uint4*)g_Wt;
        uint4* dst = (uint4*)(smem + OFF_WT);
        for (int i = tid; i < (XD * ZSTR * 2) / 16; i += THREADS) dst[i] = src[i];
    }
    for (int i = tid; i < XD; i += THREADS) biasS[i] = bdec[i];

    // ---- build z (bf16, stride 72) ----
    for (int i = tid; i < ROWS * 32; i += THREADS) {
        const int r = i >> 5, zp = i & 31;
        const int gi = (rowbase + r) * ZD + 2 * zp;
        float2 qm2 = *(const float2*)(qmu + gi);
        float2 ql2 = *(const float2*)(qls + gi);
        float2 ep2 = *(const float2*)(eps + gi);
        float z0 = fmaf(expf(ql2.x), ep2.x, qm2.x);
        float z1 = fmaf(expf(ql2.y), ep2.y, qm2.y);
        __nv_bfloat162 bv = __floats2bfloat162_rn(z0, z1);
        *(uint32_t*)(smem + OFF_ZBF + (r * ZSTR + 2 * zp) * 2) = *(uint32_t*)&bv;
    }
    __syncthreads();

    // ================= Stage 1: mean GEMM (mma.sync) + log_px ==============
    float px = 0.f;
    {
        const int g = lane >> 3, lr = lane & 7;
        uint32_t a[16];
        {
            const uint32_t aaddr = sbase + OFF_ZBF
                + (16 * wid + lr + 8 * (g & 1)) * (ZSTR * 2) + (8 * (g >> 1)) * 2;
#pragma unroll
            for (int kt = 0; kt < 4; kt++)
                ldm_x4(a[4 * kt], a[4 * kt + 1], a[4 * kt + 2], a[4 * kt + 3],
                       aaddr + kt * 32);
        }
        const uint32_t baddr0 = sbase + OFF_WT + lr * (ZSTR * 2) + (8 * g) * 2;
        const float* pxA = x + (size_t)(rowbase + 16 * wid + (lane >> 2)) * XD + 2 * (lane & 3);
        const float* pxB = pxA + 8 * XD;
        const float* bP = biasS + 2 * (lane & 3);

        uint32_t b0[8], b1[8];
        LDB(b0, 0);
        float2 bbA = *(const float2*)(bP);
        float2 xaA = *(const float2*)(pxA);
        float2 xbA = *(const float2*)(pxB);

        for (int j = 0; j < NTILES; j += 2) {
            // prefetch j+1
            LDB(b1, j + 1);
            float2 bbB = *(const float2*)(bP + 8 * (j + 1));
            float2 xaB = *(const float2*)(pxA + 8 * (j + 1));
            float2 xbB = *(const float2*)(pxB + 8 * (j + 1));
            TILE_BODY(b0, xaA, xbA, bbA);
            // prefetch j+2 (wrap-safe)
            const int jn = (j + 2 < NTILES) ? j + 2 : 0;
            LDB(b0, jn);
            bbA = *(const float2*)(bP + 8 * jn);
            xaA = *(const float2*)(pxA + 8 * jn);
            xbA = *(const float2*)(pxB + 8 * jn);
            TILE_BODY(b1, xaB, xbB, bbB);
        }
    }
    __syncthreads();

    // ---- build stage-2 arrays (overlay Wt/zbf region) ----
    float* zR = (float*)(smem + OFF_ZR);
    float* v1S = (float*)(smem + OFF_V1);
    float* qmS = (float*)(smem + OFF_QM);
    float* s2T = (float*)(smem + OFF_S2T);
    float* na2T = (float*)(smem + OFF_NA2T);
    float* compS = (float*)(smem + OFF_COMP);
    float* klzS = (float*)(smem + OFF_KLZ);

    {
        const uint4* s1 = (const uint4*)g_s2T;
        const uint4* s2 = (const uint4*)g_na2T;
        uint4* d1 = (uint4*)s2T;
        uint4* d2 = (uint4*)na2T;
        for (int i = tid; i < (ZD * KK) / 4; i += THREADS) {
            d1[i] = s1[i];
            d2[i] = s2[i];
        }
    }
    for (int i = tid; i < ROWS * ZD; i += THREADS) {
        const int r = i >> 6, z = i & 63;
        const int gi = (rowbase + r) * ZD + z;
        float qm = qmu[gi];
        float qs = expf(qls[gi]);
        zR[r * RSTR + z] = fmaf(qs, eps[gi], qm);
        v1S[r * RSTR + z] = fmaf(qs, qs, qm * qm);
        qmS[r * RSTR + z] = qm;
    }
    __syncthreads();

    // ================= Stage 2a: quadratics, tile 4r x 8k per thread =========
    {
        const int tx = tid & 7, ty = tid >> 3;
        const int kb = 8 * tx, r0 = 4 * ty;
        ull accC[4][4], accK[4][4];
#pragma unroll
        for (int r = 0; r < 4; r++)
#pragma unroll
            for (int k = 0; k < 4; k++) { accC[r][k] = 0ull; accK[r][k] = 0ull; }

        const float* s2p = s2T + kb;
        const float* nap = na2T + kb;
#pragma unroll 4
        for (int z = 0; z < ZD; z++) {
            ulonglong2 sA = *(const ulonglong2*)(s2p + z * KK);
            ulonglong2 sB = *(const ulonglong2*)(s2p + z * KK + 4);
            ulonglong2 nA = *(const ulonglong2*)(nap + z * KK);
            ulonglong2 nB = *(const ulonglong2*)(nap + z * KK + 4);
#pragma unroll
            for (int r = 0; r < 4; r++) {
                const int rb = (r0 + r) * RSTR + z;
                ull zd = dup2(zR[rb]);
                ull vd = dup2(v1S[rb]);
                ull qd = dup2(qmS[rb]);
                ull t;
                t = fma2o(sA.x, zd, nA.x); accC[r][0] = fma2o(t, zd, accC[r][0]);
                t = fma2o(sA.y, zd, nA.y); accC[r][1] = fma2o(t, zd, accC[r][1]);
                t = fma2o(sB.x, zd, nB.x); accC[r][2] = fma2o(t, zd, accC[r][2]);
                t = fma2o(sB.y, zd, nB.y); accC[r][3] = fma2o(t, zd, accC[r][3]);
                accK[r][0] = fma2o(sA.x, vd, accK[r][0]);
                accK[r][0] = fma2o(nA.x, qd, accK[r][0]);
                accK[r][1] = fma2o(sA.y, vd, accK[r][1]);
                accK[r][1] = fma2o(nA.y, qd, accK[r][1]);
                accK[r][2] = fma2o(sB.x, vd, accK[r][2]);
                accK[r][2] = fma2o(nB.x, qd, accK[r][2]);
                accK[r][3] = fma2o(sB.y, vd, accK[r][3]);
                accK[r][3] = fma2o(nB.y, qd, accK[r][3]);
            }
        }
        float cc[8], ck[8];
        *(float4*)cc = *(const float4*)(g_cc2 + kb);
        *(float4*)(cc + 4) = *(const float4*)(g_cc2 + kb + 4);
        *(float4*)ck = *(const float4*)(g_ck2 + kb);
        *(float4*)(ck + 4) = *(const float4*)(g_ck2 + kb + 4);
#pragma unroll
        for (int r = 0; r < 4; r++) {
#pragma unroll
            for (int k = 0; k < 4; k++) {
                float lo, hi;
                unpack2(accC[r][k], lo, hi);
                *(float2*)(compS + (r0 + r) * KK + kb + 2 * k) =
                    make_float2(fmaf(-0.5f, lo, cc[2 * k]), fmaf(-0.5f, hi, cc[2 * k + 1]));
                unpack2(accK[r][k], lo, hi);
                *(float2*)(klzS + (r0 + r) * KK + kb + 2 * k) =
                    make_float2(fmaf(0.5f, lo, ck[2 * k]), fmaf(0.5f, hi, ck[2 * k + 1]));
            }
        }
    }
    __syncthreads();

    // ================= Stage 2b: softmax / KL (warp per row) =========
    float kl_acc = 0.f;
    for (int rr = 0; rr < 16; rr++) {
        const int r = wid + 8 * rr;
        const int grow = rowbase + r;
        float c0 = compS[r * KK + lane];
        float c1 = compS[r * KK + lane + 32];
        float k0 = klzS[r * KK + lane];
        float k1 = klzS[r * KK + lane + 32];
        float lp0 = logf(pi[grow * KK + lane]);
        float lp1 = logf(pi[grow * KK + lane + 32]);
        float q0 = qls[grow * ZD + lane];
        float q1 = qls[grow * ZD + lane + 32];

        float qsum = q0 + q1;
#pragma unroll
        for (int o = 16; o; o >>= 1) qsum += __shfl_xor_sync(~0u, qsum, o);
        float p0 = c0 + lp0, p1 = c1 + lp1;
        float m = fmaxf(p0, p1);
#pragma unroll
        for (int o = 16; o; o >>= 1) m = fmaxf(m, __shfl_xor_sync(~0u, m, o));
        float e0 = expf(p0 - m), e1 = expf(p1 - m);
        float es = e0 + e1;
#pragma unroll
        for (int o = 16; o; o >>= 1) es += __shfl_xor_sync(~0u, es, o);
        float lse = m + logf(es);
        float inv = 1.f / es;
        float pr0 = e0 * inv, pr1 = e1 * inv;
        float contrib = pr0 * (c0 - lse) + pr1 * (c1 - lse)
                      + pr0 * (k0 - qsum - 32.f) + pr1 * (k1 - qsum - 32.f);
#pragma unroll
        for (int o = 16; o; o >>= 1) contrib += __shfl_xor_sync(~0u, contrib, o);
        if (lane == 0) kl_acc += contrib;
    }

    // ---- deterministic block + grid reduction (fixed-point atomics) ----
    float pxw = px;
#pragma unroll
    for (int o = 16; o; o >>= 1) pxw += __shfl_xor_sync(~0u, pxw, o);
    if (lane == 0) { red[wid] = pxw; red[8 + wid] = kl_acc; }
    __syncthreads();
    if (tid == 0) {
        float sp = 0.f, sk = 0.f;
#pragma unroll
        for (int w = 0; w < 8; w++) { sp += red[w]; sk += red[8 + w]; }
        const double part = (double)(-0.5f * sp - sk);
        const long long q = llrint(part * FIXSCALE);
        atomicAdd(&g_acc, (ull)q);
        __threadfence();
        const unsigned t = atomicAdd(&g_cnt, 1u);
        if (t == NBLK - 1) {
            const long long tot = (long long)atomicAdd(&g_acc, 0ull);
            out[0] = (float)((double)tot / FIXSCALE / 16384.0
                             - 0.5 * LOG2PI * (double)XD);
            g_cnt = 0u;
            g_acc = 0ull;
        }
    }
}

extern "C" void kernel_launch(void* const* d_in, const int* in_sizes, int n_in,
                              void* d_out, int out_size) {
    (void)in_sizes; (void)n_in; (void)out_size;
    const float* x    = (const float*)d_in[0];
    const float* pi   = (const float*)d_in[1];
    const float* qmu  = (const float*)d_in[2];
    const float* qls  = (const float*)d_in[3];
    const float* eps  = (const float*)d_in[4];
    const float* pmu  = (const float*)d_in[5];
    const float* pls  = (const float*)d_in[6];
    const float* W    = (const float*)d_in[7];
    const float* bdec = (const float*)d_in[8];

    cudaFuncSetAttribute(main_kernel, cudaFuncAttributeMaxDynamicSharedMemorySize,
                         SMEM_BYTES);
    prep_kernel<<<15, 256>>>(W, pmu, pls);
    main_kernel<<<NBLK, THREADS, SMEM_BYTES>>>(x, pi, qmu, qls, eps, bdec,
                                               (float*)d_out);
}